// round 16
// baseline (speedup 1.0000x reference)
#include <cuda_runtime.h>
#include <cuda_fp16.h>
#include <math.h>
#include <stdint.h>

#define BB   8
#define NN   2048
#define LL   4096
#define CC   128
#define KNB  8
#define FFD  512
#define RR2  0.04f

// ---------------- scratch (device globals; no runtime allocation) ----------
__device__ int    g_idx [BB*NN*KNB];
__device__ int    g_cnt [BB*NN];
__device__ __align__(16) __half g_SV [(size_t)BB*LL*512]; // [S0|V0|S1|V1]
__device__ __align__(16) __half g_P  [(size_t)BB*NN*CC];
__device__ __align__(16) __half g_h  [(size_t)BB*NN*FFD];
// fragment-order fp16 weights (chunk = 32x128 = 4096 halves = 8KB)
__device__ __align__(16) __half g_wda[2*4*4096];
__device__ __align__(16) __half g_wsv[16*4096];
__device__ __align__(16) float  g_bsv[512];
__device__ __align__(16) __half g_wf1[2*16*4096];
__device__ __align__(16) __half g_wf2[2*16*4096];

__device__ __forceinline__ uint32_t cvt2h(float lo, float hi) {
    uint32_t r;
    asm("cvt.rn.f16x2.f32 %0, %1, %2;" : "=r"(r) : "f"(hi), "f"(lo));
    return r;
}

__device__ __forceinline__ void mma_h(float* c, const uint32_t* a,
                                      uint32_t b0, uint32_t b1) {
    asm volatile(
        "mma.sync.aligned.m16n8k16.row.col.f32.f16.f16.f32 "
        "{%0,%1,%2,%3}, {%4,%5,%6,%7}, {%8,%9}, {%0,%1,%2,%3};"
        : "+f"(c[0]), "+f"(c[1]), "+f"(c[2]), "+f"(c[3])
        : "r"(a[0]), "r"(a[1]), "r"(a[2]), "r"(a[3]), "r"(b0), "r"(b1));
}

__device__ __forceinline__ void cp16(void* dst, const void* src) {
    uint32_t d = (uint32_t)__cvta_generic_to_shared(dst);
    asm volatile("cp.async.ca.shared.global [%0], [%1], 16;" :: "r"(d), "l"(src));
}
#define CP_COMMIT asm volatile("cp.async.commit_group;")
#define CP_WAIT1  asm volatile("cp.async.wait_group 1;")
#define CP_WAIT0  asm volatile("cp.async.wait_group 0;")

// fragment-order half offset of (k=row 0..31, col 0..127) within a chunk.
__device__ __forceinline__ int poff_h(int row, int col) {
    int s = row >> 4, kl = row & 15;
    int khigh = (kl >> 3) & 1, tig = (kl >> 1) & 3, lo = kl & 1;
    int nhalf = col >> 6, rem = col & 63;
    int u = rem >> 4, sub = rem & 15;
    int gID = sub & 7, p = sub >> 3;
    int unit = ((s*2 + nhalf)*4 + u)*32 + gID*4 + tig;
    return unit*8 + p*4 + khigh*2 + lo;
}

// ---------------- fused kNN + weight prep ------------------------------------
// blocks 0..127: kNN (b = blk>>4, ytile = blk&15), 512 threads
// blocks 128..255: prep block t = blk-128 (products / copies / cvt)
__global__ __launch_bounds__(512) void pre_kernel(
    const float* __restrict__ qxyz, const float* __restrict__ kxyz,
    const unsigned char* __restrict__ kpad,
    int* __restrict__ gidx, int* __restrict__ gcnt,
    const float* __restrict__ Wd, const float* __restrict__ Ws,
    const float* __restrict__ Wa,
    const float* __restrict__ Wlin, const float* __restrict__ blin,
    const float* __restrict__ Wf1, const float* __restrict__ Wf2,
    __half* __restrict__ Wda, __half* __restrict__ Wsv, float* __restrict__ bsv,
    __half* __restrict__ of1, __half* __restrict__ of2)
{
    extern __shared__ float sh[];
    const int tid = threadIdx.x;

    if (blockIdx.x < 128) {
        // ---------------- kNN ----------------
        float* sx = sh;                                  // [3*LL]
        unsigned char* sp = (unsigned char*)(sh + 3*LL); // [LL]
        float* md = (float*)(sp + LL);                   // [512*8]
        int*   mi = (int*)(md + 512*8);                  // [512*8]

        const int b = blockIdx.x >> 4;
        const int ytile = blockIdx.x & 15;
        for (int i = tid; i < 3*LL; i += 512)
            sx[i] = kxyz[(size_t)b*3*LL + i];
        for (int i = tid; i < LL; i += 512)
            sp[i] = kpad[(size_t)b*LL + i];
        __syncthreads();

        const int qi   = tid & 127;
        const int part = tid >> 7;
        const int q = ytile * 128 + qi;
        const float qx = qxyz[((size_t)b*NN + q)*3 + 0];
        const float qy = qxyz[((size_t)b*NN + q)*3 + 1];
        const float qz = qxyz[((size_t)b*NN + q)*3 + 2];

        float bd[KNB]; int bi[KNB];
#pragma unroll
        for (int k = 0; k < KNB; k++) { bd[k] = 1e30f; bi[k] = 0; }

        const int j0 = part * (LL/4), j1 = j0 + LL/4;
        for (int j = j0; j < j1; j++) {
            float dx = sx[3*j+0] - qx;
            float dy = sx[3*j+1] - qy;
            float dz = sx[3*j+2] - qz;
            float d2 = fmaf(dx, dx, fmaf(dy, dy, dz*dz));
            if (d2 <= RR2 && d2 < bd[KNB-1] && !sp[j]) {
                float v = d2; int vi = j;
#pragma unroll
                for (int k = 0; k < KNB; k++) {
                    if (v < bd[k]) {
                        float tf = bd[k]; bd[k] = v; v = tf;
                        int   ti = bi[k]; bi[k] = vi; vi = ti;
                    }
                }
            }
        }
#pragma unroll
        for (int k = 0; k < KNB; k++) {
            md[(qi*4 + part)*8 + k] = bd[k];
            mi[(qi*4 + part)*8 + k] = bi[k];
        }
        __syncthreads();

        if (part == 0) {
            float fb[KNB]; int fi[KNB];
#pragma unroll
            for (int k = 0; k < KNB; k++) { fb[k] = 1e30f; fi[k] = 0; }
            for (int p = 0; p < 4; p++) {
                for (int k = 0; k < KNB; k++) {
                    float v = md[(qi*4 + p)*8 + k];
                    if (v >= fb[KNB-1]) break;
                    int vi = mi[(qi*4 + p)*8 + k];
#pragma unroll
                    for (int t = 0; t < KNB; t++) {
                        if (v < fb[t]) {
                            float tf = fb[t]; fb[t] = v; v = tf;
                            int   ti = fi[t]; fi[t] = vi; vi = ti;
                        }
                    }
                }
            }
            int cnt = 0;
#pragma unroll
            for (int k = 0; k < KNB; k++) cnt += (fb[k] <= RR2) ? 1 : 0;
#pragma unroll
            for (int k = 0; k < KNB; k++)
                gidx[((size_t)b*NN + q)*KNB + k] = fi[k];
            gcnt[b*NN + q] = cnt;
        }
    } else {
        // ---------------- weight prep ----------------
        const int t = blockIdx.x - 128;
        float* sA = sh;                                  // [64*132]

        if (t < 32) {
            const int p = t >> 3;
            const int layer = p >> 1;
            const float* A  = ((p & 1) ? Ws : Wd) + (size_t)layer*CC*CC;
            const float* Wm = Wa + (size_t)layer*CC*CC;
            const int r0 = ((t>>2)&1) * 64;
            const int n0 = (t&3) * 32;

            for (int i = tid; i < 64*32; i += 512) {
                int row = i >> 5, c4 = (i & 31) * 4;
                float4 v = *(const float4*)&A[(size_t)(r0+row)*CC + c4];
                sA[row*132 + c4+0] = v.x;
                sA[row*132 + c4+1] = v.y;
                sA[row*132 + c4+2] = v.z;
                sA[row*132 + c4+3] = v.w;
            }
            __syncthreads();

            if (tid < 256) {
                const int c  = n0 + (tid & 31);
                const int rr = (tid >> 5) * 8;
                float acc[8] = {0.f,0.f,0.f,0.f,0.f,0.f,0.f,0.f};
                for (int kk = 0; kk < 128; kk++) {
                    float w = Wm[(size_t)kk*CC + c];
#pragma unroll
                    for (int i = 0; i < 8; i++)
                        acc[i] = fmaf(sA[(rr+i)*132 + kk], w, acc[i]);
                }
#pragma unroll
                for (int i = 0; i < 8; i++) {
                    int row = r0 + rr + i;
                    int kc = row >> 5;
                    if (p & 1) {
                        int nc = 2*layer;
                        Wsv[(size_t)(nc*4 + kc)*4096 + poff_h(row & 31, c)] =
                            __float2half_rn(acc[i]);
                    } else {
                        Wda[(size_t)(layer*4 + kc)*4096 + poff_h(row & 31, c)] =
                            __float2half_rn(acc[i]);
                    }
                }
            }
        } else if (t < 64) {
            if (tid < 256) {
                const int tt = t - 32;
                const int l = tt >> 4, bx = tt & 15;
                for (int i = bx*256 + tid; i < CC*CC; i += 16*256) {
                    int row = i >> 7, c = i & 127;
                    int nc = 2*l + 1, kc = row >> 5;
                    Wsv[(size_t)(nc*4 + kc)*4096 + poff_h(row & 31, c)] =
                        __float2half_rn(Wlin[(size_t)l*CC*CC + i]);
                }
                if (bx == 0) {
                    for (int i = tid; i < 128; i += 256) {
                        bsv[256*l + i]       = 0.f;
                        bsv[256*l + 128 + i] = blin[l*CC + i];
                    }
                }
            }
        } else {
            if (tid < 256) {
                const int bx = t - 64;
                const int n = 2*CC*FFD;
                for (int i = bx*256 + tid; i < n; i += 64*256) {
                    {
                        int l = i >> 16, r2 = i & 65535;
                        int row = r2 >> 9, col = r2 & 511;
                        int nc = col >> 7, kc = row >> 5;
                        of1[(size_t)l*65536 + (size_t)(nc*4 + kc)*4096
                            + poff_h(row & 31, col & 127)] = __float2half_rn(Wf1[i]);
                    }
                    {
                        int l = i >> 16, r2 = i & 65535;
                        int row = r2 >> 7, col = r2 & 127;
                        int kc = row >> 5;
                        of2[(size_t)l*65536 + (size_t)kc*4096
                            + poff_h(row & 31, col)] = __float2half_rn(Wf2[i]);
                    }
                }
            }
        }
    }
}

// ---------------- merged SV (both layers) + P(layer0) GEMM ------------------
// grid (256, 5): y<4 -> SV tile y of kv_feat@WSV (Ncols 512);
//                y==4, x<128 -> P = q_feat@Wda0 + b_attn (Ncols 128).
// fp32 A converted at fragment load; fp16 out. MT=128, KD=128.
__global__ __launch_bounds__(256, 2) void gemm_svp(
    const float* __restrict__ Asv, const __half* __restrict__ Wsv,
    const float* __restrict__ bsv, __half* __restrict__ Csv,
    const float* __restrict__ Ap,  const __half* __restrict__ Wp,
    const float* __restrict__ bp,  __half* __restrict__ Cp)
{
    constexpr int AF = 128 * 40;
    constexpr int WF = 2048;
    extern __shared__ float dynsm[];
    float* Abuf[2]  = { dynsm,      dynsm + AF + WF };
    float* Wbuf[2]  = { dynsm + AF, dynsm + 2*AF + WF };

    const float* A; const __half* W; const float* bias; __half* C;
    int Ncols, n0;
    if (blockIdx.y < 4) {
        A = Asv; W = Wsv; bias = bsv; C = Csv; Ncols = 512; n0 = blockIdx.y*128;
    } else {
        if (blockIdx.x >= 128) return;
        A = Ap; W = Wp; bias = bp; C = Cp; Ncols = 128; n0 = 0;
    }

    const int m0 = blockIdx.x * 128;
    const int tid = threadIdx.x;
    const int lane = tid & 31, warp = tid >> 5;
    const int wm = (warp & 3) * 32, wn = (warp >> 2) * 64;
    const int nhalf = warp >> 2;
    const int gID = lane >> 2, tig = lane & 3;

    const __half* Wbase = W + (size_t)(n0 >> 7) * 4 * 4096;

    float acc[2][8][4];
#pragma unroll
    for (int mt = 0; mt < 2; mt++)
#pragma unroll
        for (int nt = 0; nt < 8; nt++)
#pragma unroll
            for (int c = 0; c < 4; c++) acc[mt][nt][c] = 0.f;

    auto issue = [&](int st, int ic) {
        const int kc = ic * 32;
#pragma unroll
        for (int r = 0; r < 4; r++) {
            int id = tid + r*256;
            int row = id >> 3, c4 = (id & 7) * 4;
            cp16(&Abuf[st][row*40 + c4], &A[(size_t)(m0+row)*128 + kc + c4]);
        }
        const __half* wsrc = Wbase + (size_t)ic * 4096;
#pragma unroll
        for (int r = 0; r < 2; r++) {
            int id = tid + r*256;
            cp16(&Wbuf[st][id*4], (const float*)(wsrc + id*8));
        }
    };

    issue(0, 0);
    CP_COMMIT;

    for (int it = 0; it < 4; ++it) {
        if (it + 1 < 4) { issue((it+1) & 1, it+1); CP_COMMIT; CP_WAIT1; }
        else CP_WAIT0;
        __syncthreads();
        const float*  Ac = Abuf[it & 1];
        const float4* Wf4 = (const float4*)Wbuf[it & 1];
#pragma unroll
        for (int s = 0; s < 2; s++) {
            uint32_t a[2][4];
#pragma unroll
            for (int mt = 0; mt < 2; mt++) {
                int r0 = wm + mt*16 + gID;
                const float* b0p = &Ac[r0*40 + s*16 + 2*tig];
                const float* b1p = &Ac[(r0+8)*40 + s*16 + 2*tig];
                float2 p0 = *(const float2*)b0p;
                float2 p1 = *(const float2*)b1p;
                float2 p2 = *(const float2*)(b0p + 8);
                float2 p3 = *(const float2*)(b1p + 8);
                a[mt][0] = cvt2h(p0.x, p0.y);
                a[mt][1] = cvt2h(p1.x, p1.y);
                a[mt][2] = cvt2h(p2.x, p2.y);
                a[mt][3] = cvt2h(p3.x, p3.y);
            }
#pragma unroll
            for (int u = 0; u < 4; u++) {
                float4 bq = Wf4[((s*2 + nhalf)*4 + u)*32 + lane];
                uint32_t be0 = __float_as_uint(bq.x), be1 = __float_as_uint(bq.y);
                uint32_t bo0 = __float_as_uint(bq.z), bo1 = __float_as_uint(bq.w);
#pragma unroll
                for (int mt = 0; mt < 2; mt++) {
                    mma_h(acc[mt][2*u],   a[mt], be0, be1);
                    mma_h(acc[mt][2*u+1], a[mt], bo0, bo1);
                }
            }
        }
        if (it + 1 < 4) __syncthreads();
    }

#pragma unroll
    for (int mt = 0; mt < 2; mt++) {
        int row = m0 + wm + mt*16 + gID;
#pragma unroll
        for (int nt = 0; nt < 8; nt++) {
            int col = n0 + wn + nt*8 + 2*tig;
            float b0v = bias[col], b1v = bias[col+1];
            *(__half2*)&C[(size_t)row*Ncols + col] =
                __floats2half2_rn(acc[mt][nt][0]+b0v, acc[mt][nt][1]+b1v);
            *(__half2*)&C[(size_t)(row+8)*Ncols + col] =
                __floats2half2_rn(acc[mt][nt][2]+b0v, acc[mt][nt][3]+b1v);
        }
    }
}

// ---------------- fp16 tensor-core GEMM, permuted-B, cp.async ---------------
// AH=0: A fp32 (smem stride 40 floats). AH=1: A fp16 (smem stride 56 halves).
// EPI: 0 = (+bias, fp16 out), 1 = (+bias, exact GELU, fp16 out),
//      2 = (+bias, +resid fp32, LayerNorm, fp32 out)
template<int KD, int MT, int EPI, int AH>
__global__ __launch_bounds__(256, 2) void gemm_h(
    const void* __restrict__ Ain, const __half* __restrict__ W,
    const float* __restrict__ bias, void* __restrict__ Cout, int Ncols,
    const float* __restrict__ resid,
    const float* __restrict__ lng, const float* __restrict__ lnb)
{
    constexpr int MTC = MT / 64;
    constexpr int AF = AH ? (MT * 28) : (MT * 40);
    constexpr int WF = 2048;
    extern __shared__ float dynsm[];
    float* Abuf[2]  = { dynsm,      dynsm + AF + WF };
    float* Wbuf[2]  = { dynsm + AF, dynsm + 2*AF + WF };
    __shared__ float rs1[128], rs2[128];

    const int m0 = blockIdx.x * MT;
    const int n0 = blockIdx.y * 128;
    const int tid = threadIdx.x;
    const int lane = tid & 31, warp = tid >> 5;
    const int wm = (warp & 3) * (MT/4), wn = (warp >> 2) * 64;
    const int nhalf = warp >> 2;
    const int gID = lane >> 2, tig = lane & 3;

    if (EPI == 2 && tid < MT) { rs1[tid] = 0.f; rs2[tid] = 0.f; }

    const __half* Wbase = W + (size_t)(n0 >> 7) * (KD/32) * 4096;
    const float*  Af = (const float*)Ain;
    const __half* Ah = (const __half*)Ain;

    float acc[MTC][8][4];
#pragma unroll
    for (int mt = 0; mt < MTC; mt++)
#pragma unroll
        for (int nt = 0; nt < 8; nt++)
#pragma unroll
            for (int c = 0; c < 4; c++) acc[mt][nt][c] = 0.f;

    auto issue = [&](int st, int ic) {
        const int kc = ic * 32;
        if (AH == 0) {
#pragma unroll
            for (int r = 0; r < MT/32; r++) {
                int id = tid + r*256;
                int row = id >> 3, c4 = (id & 7) * 4;
                cp16(&Abuf[st][row*40 + c4], &Af[(size_t)(m0+row)*KD + kc + c4]);
            }
        } else {
            __half* Ab = (__half*)Abuf[st];
#pragma unroll
            for (int r = 0; r < MT/64; r++) {
                int id = tid + r*256;
                int row = id >> 2, u = (id & 3) * 8;
                cp16(&Ab[row*56 + u], &Ah[(size_t)(m0+row)*KD + kc + u]);
            }
        }
        const __half* wsrc = Wbase + (size_t)ic * 4096;
#pragma unroll
        for (int r = 0; r < 2; r++) {
            int id = tid + r*256;
            cp16(&Wbuf[st][id*4], (const float*)(wsrc + id*8));
        }
    };

    constexpr int NIT = KD / 32;
    issue(0, 0);
    CP_COMMIT;

    for (int it = 0; it < NIT; ++it) {
        if (it + 1 < NIT) { issue((it+1) & 1, it+1); CP_COMMIT; CP_WAIT1; }
        else CP_WAIT0;
        __syncthreads();
        const float*  Ac = Abuf[it & 1];
        const __half* Ach = (const __half*)Abuf[it & 1];
        const float4* Wf4 = (const float4*)Wbuf[it & 1];
#pragma unroll
        for (int s = 0; s < 2; s++) {
            uint32_t a[MTC][4];
#pragma unroll
            for (int mt = 0; mt < MTC; mt++) {
                int r0 = wm + mt*16 + gID;
                if (AH == 0) {
                    const float* b0p = &Ac[r0*40 + s*16 + 2*tig];
                    const float* b1p = &Ac[(r0+8)*40 + s*16 + 2*tig];
                    float2 p0 = *(const float2*)b0p;
                    float2 p1 = *(const float2*)b1p;
                    float2 p2 = *(const float2*)(b0p + 8);
                    float2 p3 = *(const float2*)(b1p + 8);
                    a[mt][0] = cvt2h(p0.x, p0.y);
                    a[mt][1] = cvt2h(p1.x, p1.y);
                    a[mt][2] = cvt2h(p2.x, p2.y);
                    a[mt][3] = cvt2h(p3.x, p3.y);
                } else {
                    a[mt][0] = *(const uint32_t*)&Ach[r0*56 + s*16 + 2*tig];
                    a[mt][1] = *(const uint32_t*)&Ach[(r0+8)*56 + s*16 + 2*tig];
                    a[mt][2] = *(const uint32_t*)&Ach[r0*56 + s*16 + 2*tig + 8];
                    a[mt][3] = *(const uint32_t*)&Ach[(r0+8)*56 + s*16 + 2*tig + 8];
                }
            }
#pragma unroll
            for (int u = 0; u < 4; u++) {
                float4 bq = Wf4[((s*2 + nhalf)*4 + u)*32 + lane];
                uint32_t be0 = __float_as_uint(bq.x), be1 = __float_as_uint(bq.y);
                uint32_t bo0 = __float_as_uint(bq.z), bo1 = __float_as_uint(bq.w);
#pragma unroll
                for (int mt = 0; mt < MTC; mt++) {
                    mma_h(acc[mt][2*u],   a[mt], be0, be1);
                    mma_h(acc[mt][2*u+1], a[mt], bo0, bo1);
                }
            }
        }
        if (it + 1 < NIT) __syncthreads();
    }

    if (EPI != 2) {
        __half* Ch = (__half*)Cout;
#pragma unroll
        for (int mt = 0; mt < MTC; mt++) {
            int row = m0 + wm + mt*16 + gID;
#pragma unroll
            for (int nt = 0; nt < 8; nt++) {
                int col = n0 + wn + nt*8 + 2*tig;
                float b0v = bias ? bias[col]   : 0.f;
                float b1v = bias ? bias[col+1] : 0.f;
                float v0 = acc[mt][nt][0] + b0v;
                float v1 = acc[mt][nt][1] + b1v;
                float v2 = acc[mt][nt][2] + b0v;
                float v3 = acc[mt][nt][3] + b1v;
                if (EPI == 1) {
                    v0 = 0.5f*v0*(1.f + erff(v0*0.70710678118654752f));
                    v1 = 0.5f*v1*(1.f + erff(v1*0.70710678118654752f));
                    v2 = 0.5f*v2*(1.f + erff(v2*0.70710678118654752f));
                    v3 = 0.5f*v3*(1.f + erff(v3*0.70710678118654752f));
                }
                *(__half2*)&Ch[(size_t)row*Ncols + col] =
                    __floats2half2_rn(v0, v1);
                *(__half2*)&Ch[(size_t)(row+8)*Ncols + col] =
                    __floats2half2_rn(v2, v3);
            }
        }
    } else {
        float* Cf = (float*)Cout;
        float s1[MTC][2], s2[MTC][2];
#pragma unroll
        for (int mt = 0; mt < MTC; mt++) {
            s1[mt][0]=s1[mt][1]=s2[mt][0]=s2[mt][1]=0.f;
            int row = m0 + wm + mt*16 + gID;
#pragma unroll
            for (int nt = 0; nt < 8; nt++) {
                int col = wn + nt*8 + 2*tig;
                float b0v = bias[col], b1v = bias[col+1];
                float x0 = acc[mt][nt][0] + b0v + resid[(size_t)row*128 + col];
                float x1 = acc[mt][nt][1] + b1v + resid[(size_t)row*128 + col+1];
                float x2 = acc[mt][nt][2] + b0v + resid[(size_t)(row+8)*128 + col];
                float x3 = acc[mt][nt][3] + b1v + resid[(size_t)(row+8)*128 + col+1];
                acc[mt][nt][0]=x0; acc[mt][nt][1]=x1; acc[mt][nt][2]=x2; acc[mt][nt][3]=x3;
                s1[mt][0] += x0 + x1;       s1[mt][1] += x2 + x3;
                s2[mt][0] += x0*x0 + x1*x1; s2[mt][1] += x2*x2 + x3*x3;
            }
        }
#pragma unroll
        for (int mt = 0; mt < MTC; mt++)
#pragma unroll
            for (int h = 0; h < 2; h++) {
                s1[mt][h] += __shfl_xor_sync(0xffffffffu, s1[mt][h], 1);
                s1[mt][h] += __shfl_xor_sync(0xffffffffu, s1[mt][h], 2);
                s2[mt][h] += __shfl_xor_sync(0xffffffffu, s2[mt][h], 1);
                s2[mt][h] += __shfl_xor_sync(0xffffffffu, s2[mt][h], 2);
            }
        if (tig == 0) {
#pragma unroll
            for (int mt = 0; mt < MTC; mt++)
#pragma unroll
                for (int h = 0; h < 2; h++) {
                    int lr = wm + mt*16 + gID + h*8;
                    atomicAdd(&rs1[lr], s1[mt][h]);
                    atomicAdd(&rs2[lr], s2[mt][h]);
                }
        }
        __syncthreads();
#pragma unroll
        for (int mt = 0; mt < MTC; mt++) {
            int lr = wm + mt*16 + gID;
            float mu0 = rs1[lr]   * (1.f/128.f);
            float mu1 = rs1[lr+8] * (1.f/128.f);
            float rstd0 = rsqrtf(rs2[lr]  *(1.f/128.f) - mu0*mu0 + 1e-5f);
            float rstd1 = rsqrtf(rs2[lr+8]*(1.f/128.f) - mu1*mu1 + 1e-5f);
            int row = m0 + lr;
#pragma unroll
            for (int nt = 0; nt < 8; nt++) {
                int col = wn + nt*8 + 2*tig;
                float g0 = lng[col], g1 = lng[col+1];
                float bb0 = lnb[col], bb1 = lnb[col+1];
                float y0 = (acc[mt][nt][0]-mu0)*rstd0*g0 + bb0;
                float y1 = (acc[mt][nt][1]-mu0)*rstd0*g1 + bb1;
                float y2 = (acc[mt][nt][2]-mu1)*rstd1*g0 + bb0;
                float y3 = (acc[mt][nt][3]-mu1)*rstd1*g1 + bb1;
                *(float2*)&Cf[(size_t)row*128 + col]     = make_float2(y0, y1);
                *(float2*)&Cf[(size_t)(row+8)*128 + col] = make_float2(y2, y3);
            }
        }
    }
}

// ---------------- light attention: gather + softmax + residual + LN ---------
__global__ __launch_bounds__(256) void attn2_kernel(
    const __half* __restrict__ P, const __half* __restrict__ S,
    const __half* __restrict__ V, const int* __restrict__ gidx,
    const int* __restrict__ gcnt,
    const float* __restrict__ resid, float* __restrict__ out,
    const float* __restrict__ g1, const float* __restrict__ b1)
{
    const int warp = threadIdx.x >> 5, lane = threadIdx.x & 31;
    const int q = blockIdx.x * 8 + warp;
    const int b = q / NN;
    const int c0 = lane * 4;

    const __half2* pp = (const __half2*)&P[(size_t)q*CC + c0];
    float2 pa = __half22float2(pp[0]);
    float2 pb = __half22float2(pp[1]);
    const int kcnt = gcnt[q];
    int nid[KNB];
#pragma unroll
    for (int k = 0; k < KNB; k++) nid[k] = gidx[(size_t)q*KNB + k];

    float4 lg[KNB];
    float mx0 = -1e30f, mx1 = -1e30f, mx2 = -1e30f, mx3 = -1e30f;
#pragma unroll
    for (int k = 0; k < KNB; k++) {
        if (k < kcnt) {
            const __half2* sp2 = (const __half2*)&S[((size_t)b*LL + nid[k])*512 + c0];
            float2 sa = __half22float2(sp2[0]);
            float2 sb = __half22float2(sp2[1]);
            float4 l;
            l.x = fmaxf(pa.x - sa.x, 0.f);
            l.y = fmaxf(pa.y - sa.y, 0.f);
            l.z = fmaxf(pb.x - sb.x, 0.f);
            l.w = fmaxf(pb.y - sb.y, 0.f);
            lg[k] = l;
            mx0 = fmaxf(mx0, l.x); mx1 = fmaxf(mx1, l.y);
            mx2 = fmaxf(mx2, l.z); mx3 = fmaxf(mx3, l.w);
        }
    }

    float su0=0.f, su1=0.f, su2=0.f, su3=0.f;
    float up0=0.f, up1=0.f, up2=0.f, up3=0.f;
#pragma unroll
    for (int k = 0; k < KNB; k++) {
        if (k < kcnt) {
            const __half2* vp2 = (const __half2*)&V[((size_t)b*LL + nid[k])*512 + c0];
            float2 va = __half22float2(vp2[0]);
            float2 vb = __half22float2(vp2[1]);
            float w0 = expf(lg[k].x - mx0);
            float w1 = expf(lg[k].y - mx1);
            float w2 = expf(lg[k].z - mx2);
            float w3 = expf(lg[k].w - mx3);
            su0 += w0; su1 += w1; su2 += w2; su3 += w3;
            up0 = fmaf(w0, va.x, up0);
            up1 = fmaf(w1, va.y, up1);
            up2 = fmaf(w2, vb.x, up2);
            up3 = fmaf(w3, vb.y, up3);
        }
    }
    up0 /= fmaxf(su0, 1e-9f);
    up1 /= fmaxf(su1, 1e-9f);
    up2 /= fmaxf(su2, 1e-9f);
    up3 /= fmaxf(su3, 1e-9f);

    const float4 r4 = *(const float4*)&resid[(size_t)q*CC + c0];
    float x0 = r4.x + up0, x1 = r4.y + up1, x2 = r4.z + up2, x3 = r4.w + up3;

    float s = x0 + x1 + x2 + x3;
#pragma unroll
    for (int o = 16; o; o >>= 1) s += __shfl_xor_sync(0xffffffffu, s, o);
    float mu = s * (1.f/128.f);
    float d0 = x0-mu, d1 = x1-mu, d2 = x2-mu, d3 = x3-mu;
    float vs = d0*d0 + d1*d1 + d2*d2 + d3*d3;
#pragma unroll
    for (int o = 16; o; o >>= 1) vs += __shfl_xor_sync(0xffffffffu, vs, o);
    float rstd = rsqrtf(vs * (1.f/128.f) + 1e-5f);

    const float4 gg = *(const float4*)&g1[c0];
    const float4 bb = *(const float4*)&b1[c0];
    float4 y;
    y.x = d0*rstd*gg.x + bb.x;
    y.y = d1*rstd*gg.y + bb.y;
    y.z = d2*rstd*gg.z + bb.z;
    y.w = d3*rstd*gg.w + bb.w;
    *(float4*)&out[(size_t)q*CC + c0] = y;
}

// ---------------- launch ----------------------------------------------------
extern "C" void kernel_launch(void* const* d_in, const int* in_sizes, int n_in,
                              void* d_out, int out_size)
{
    const float*         q_xyz  = (const float*)d_in[0];
    const float*         q_feat = (const float*)d_in[1];
    const float*         kv_xyz = (const float*)d_in[2];
    const float*         kv_feat= (const float*)d_in[3];
    const unsigned char* kv_pad = (const unsigned char*)d_in[4];
    const float* W_lin  = (const float*)d_in[5];
    const float* b_lin  = (const float*)d_in[6];
    const float* W_src  = (const float*)d_in[7];
    const float* W_dst  = (const float*)d_in[8];
    const float* W_attn = (const float*)d_in[9];
    const float* b_attn = (const float*)d_in[10];
    const float* ln1_g  = (const float*)d_in[11];
    const float* ln1_b  = (const float*)d_in[12];
    const float* W_ff1  = (const float*)d_in[13];
    const float* b_ff1  = (const float*)d_in[14];
    const float* W_ff2  = (const float*)d_in[15];
    const float* b_ff2  = (const float*)d_in[16];
    const float* ln2_g  = (const float*)d_in[17];
    const float* ln2_b  = (const float*)d_in[18];
    float* out = (float*)d_out;

    void *p_idx, *p_cnt, *p_sv, *p_P, *p_h, *p_wda, *p_wsv, *p_bsv, *p_wf1, *p_wf2;
    cudaGetSymbolAddress(&p_idx, g_idx);
    cudaGetSymbolAddress(&p_cnt, g_cnt);
    cudaGetSymbolAddress(&p_sv,  g_SV);
    cudaGetSymbolAddress(&p_P,   g_P);
    cudaGetSymbolAddress(&p_h,   g_h);
    cudaGetSymbolAddress(&p_wda, g_wda);
    cudaGetSymbolAddress(&p_wsv, g_wsv);
    cudaGetSymbolAddress(&p_bsv, g_bsv);
    cudaGetSymbolAddress(&p_wf1, g_wf1);
    cudaGetSymbolAddress(&p_wf2, g_wf2);
    int*    idx_p = (int*)p_idx;
    int*    cnt_p = (int*)p_cnt;
    __half* sv_p  = (__half*)p_sv;
    __half* P_p   = (__half*)p_P;
    __half* h_p   = (__half*)p_h;
    __half* wda_p = (__half*)p_wda;
    __half* wsv_p = (__half*)p_wsv;
    float*  bsv_p = (float*)p_bsv;
    __half* wf1_p = (__half*)p_wf1;
    __half* wf2_p = (__half*)p_wf2;

    const int PRE_SMEM = 3*LL*4 + LL + 512*8*4*2;            // 86016
    const int SM128A0 = (2*(128*40) + 2*2048)*4;             // 57344
    const int SM64A0  = (2*(64*40)  + 2*2048)*4;             // 36864
    const int SM64A1  = (2*(64*28)  + 2*2048)*4;             // 30720
    cudaFuncSetAttribute(pre_kernel, cudaFuncAttributeMaxDynamicSharedMemorySize, PRE_SMEM);
    cudaFuncSetAttribute(gemm_svp,            cudaFuncAttributeMaxDynamicSharedMemorySize, SM128A0);
    cudaFuncSetAttribute(gemm_h<128,128,1,0>, cudaFuncAttributeMaxDynamicSharedMemorySize, SM128A0);
    cudaFuncSetAttribute(gemm_h<128,64,0,0>,  cudaFuncAttributeMaxDynamicSharedMemorySize, SM64A0);
    cudaFuncSetAttribute(gemm_h<512,64,2,1>,  cudaFuncAttributeMaxDynamicSharedMemorySize, SM64A1);

    const int BN = BB*NN;   // 16384

    // fused kNN + weight prep (one launch)
    pre_kernel<<<256, 512, PRE_SMEM>>>(
        q_xyz, kv_xyz, kv_pad, idx_p, cnt_p,
        W_dst, W_src, W_attn, W_lin, b_lin, W_ff1, W_ff2,
        wda_p, wsv_p, bsv_p, wf1_p, wf2_p);

    // merged: SV (both layers) + P(layer 0)
    gemm_svp<<<dim3(256, 5), 256, SM128A0>>>(
        kv_feat, wsv_p, bsv_p, sv_p,
        q_feat, wda_p, b_attn, P_p);

    for (int l = 0; l < 2; l++) {
        const size_t oC  = (size_t)l * CC;
        const size_t oF  = (size_t)l * FFD;
        const float* in_l = (l == 0) ? q_feat : out;

        if (l == 1) {
            // P = out @ Wda1 + b_attn1  (fp16 out)
            gemm_h<128,64,0,0><<<dim3(BN/64, 1), 256, SM64A0>>>(
                out, wda_p + (size_t)4*4096, b_attn + oC, P_p, CC,
                nullptr, nullptr, nullptr);
        }
        // attention gather/softmax + residual + LN1
        attn2_kernel<<<BN/8, 256>>>(
            P_p, sv_p + 256*l, sv_p + 256*l + 128, idx_p, cnt_p,
            in_l, out, ln1_g + oC, ln1_b + oC);
        // h = gelu(out @ W_ff1 + b_ff1)  (fp16 out)
        gemm_h<128,128,1,0><<<dim3(BN/128, FFD/128), 256, SM128A0>>>(
            out, wf1_p + (size_t)l*65536, b_ff1 + oF, h_p, FFD,
            nullptr, nullptr, nullptr);
        // out = LN2(out + h @ W_ff2 + b_ff2)  (A = h fp16)
        gemm_h<512,64,2,1><<<dim3(BN/64, 1), 256, SM64A1>>>(
            h_p, wf2_p + (size_t)l*65536, b_ff2 + oC, out, CC,
            out, ln2_g + oC, ln2_b + oC);
    }
}

// round 17
// speedup vs baseline: 1.0065x; 1.0065x over previous
#include <cuda_runtime.h>
#include <cuda_fp16.h>
#include <math.h>
#include <stdint.h>

#define BB   8
#define NN   2048
#define LL   4096
#define CC   128
#define KNB  8
#define FFD  512
#define RR2  0.04f

// ---------------- scratch (device globals; no runtime allocation) ----------
__device__ int    g_idx [BB*NN*KNB];
__device__ int    g_cnt [BB*NN];
__device__ __align__(16) __half g_SV [(size_t)BB*LL*512]; // [S0|V0|S1|V1]
__device__ __align__(16) __half g_P  [(size_t)BB*NN*CC];
__device__ __align__(16) __half g_h  [(size_t)BB*NN*FFD];
// fragment-order fp16 weights (chunk = 32x128 = 4096 halves = 8KB)
__device__ __align__(16) __half g_wda[2*4*4096];
__device__ __align__(16) __half g_wsv[16*4096];
__device__ __align__(16) float  g_bsv[512];
__device__ __align__(16) __half g_wf1[2*16*4096];
__device__ __align__(16) __half g_wf2[2*16*4096];

__device__ __forceinline__ uint32_t cvt2h(float lo, float hi) {
    uint32_t r;
    asm("cvt.rn.f16x2.f32 %0, %1, %2;" : "=r"(r) : "f"(hi), "f"(lo));
    return r;
}

__device__ __forceinline__ void mma_h(float* c, const uint32_t* a,
                                      uint32_t b0, uint32_t b1) {
    asm volatile(
        "mma.sync.aligned.m16n8k16.row.col.f32.f16.f16.f32 "
        "{%0,%1,%2,%3}, {%4,%5,%6,%7}, {%8,%9}, {%0,%1,%2,%3};"
        : "+f"(c[0]), "+f"(c[1]), "+f"(c[2]), "+f"(c[3])
        : "r"(a[0]), "r"(a[1]), "r"(a[2]), "r"(a[3]), "r"(b0), "r"(b1));
}

__device__ __forceinline__ void cp16(void* dst, const void* src) {
    uint32_t d = (uint32_t)__cvta_generic_to_shared(dst);
    asm volatile("cp.async.ca.shared.global [%0], [%1], 16;" :: "r"(d), "l"(src));
}
#define CP_COMMIT asm volatile("cp.async.commit_group;")
#define CP_WAIT1  asm volatile("cp.async.wait_group 1;")
#define CP_WAIT0  asm volatile("cp.async.wait_group 0;")

// fragment-order half offset of (k=row 0..31, col 0..127) within a chunk.
__device__ __forceinline__ int poff_h(int row, int col) {
    int s = row >> 4, kl = row & 15;
    int khigh = (kl >> 3) & 1, tig = (kl >> 1) & 3, lo = kl & 1;
    int nhalf = col >> 6, rem = col & 63;
    int u = rem >> 4, sub = rem & 15;
    int gID = sub & 7, p = sub >> 3;
    int unit = ((s*2 + nhalf)*4 + u)*32 + gID*4 + tig;
    return unit*8 + p*4 + khigh*2 + lo;
}

// ---------------- fused kNN + weight prep ------------------------------------
// blocks 0..127: kNN (b = blk>>4, ytile = blk&15), 512 threads
// blocks 128..255: prep block t = blk-128 (products / copies / cvt)
__global__ __launch_bounds__(512) void pre_kernel(
    const float* __restrict__ qxyz, const float* __restrict__ kxyz,
    const unsigned char* __restrict__ kpad,
    int* __restrict__ gidx, int* __restrict__ gcnt,
    const float* __restrict__ Wd, const float* __restrict__ Ws,
    const float* __restrict__ Wa,
    const float* __restrict__ Wlin, const float* __restrict__ blin,
    const float* __restrict__ Wf1, const float* __restrict__ Wf2,
    __half* __restrict__ Wda, __half* __restrict__ Wsv, float* __restrict__ bsv,
    __half* __restrict__ of1, __half* __restrict__ of2)
{
    extern __shared__ float sh[];
    const int tid = threadIdx.x;

    if (blockIdx.x < 128) {
        // ---------------- kNN ----------------
        float* sx = sh;                                  // [3*LL]
        unsigned char* sp = (unsigned char*)(sh + 3*LL); // [LL]
        float* md = (float*)(sp + LL);                   // [512*8]
        int*   mi = (int*)(md + 512*8);                  // [512*8]

        const int b = blockIdx.x >> 4;
        const int ytile = blockIdx.x & 15;
        for (int i = tid; i < 3*LL; i += 512)
            sx[i] = kxyz[(size_t)b*3*LL + i];
        for (int i = tid; i < LL; i += 512)
            sp[i] = kpad[(size_t)b*LL + i];
        __syncthreads();

        const int qi   = tid & 127;
        const int part = tid >> 7;
        const int q = ytile * 128 + qi;
        const float qx = qxyz[((size_t)b*NN + q)*3 + 0];
        const float qy = qxyz[((size_t)b*NN + q)*3 + 1];
        const float qz = qxyz[((size_t)b*NN + q)*3 + 2];

        float bd[KNB]; int bi[KNB];
#pragma unroll
        for (int k = 0; k < KNB; k++) { bd[k] = 1e30f; bi[k] = 0; }

        const int j0 = part * (LL/4), j1 = j0 + LL/4;
        for (int j = j0; j < j1; j++) {
            float dx = sx[3*j+0] - qx;
            float dy = sx[3*j+1] - qy;
            float dz = sx[3*j+2] - qz;
            float d2 = fmaf(dx, dx, fmaf(dy, dy, dz*dz));
            if (d2 <= RR2 && d2 < bd[KNB-1] && !sp[j]) {
                float v = d2; int vi = j;
#pragma unroll
                for (int k = 0; k < KNB; k++) {
                    if (v < bd[k]) {
                        float tf = bd[k]; bd[k] = v; v = tf;
                        int   ti = bi[k]; bi[k] = vi; vi = ti;
                    }
                }
            }
        }
#pragma unroll
        for (int k = 0; k < KNB; k++) {
            md[(qi*4 + part)*8 + k] = bd[k];
            mi[(qi*4 + part)*8 + k] = bi[k];
        }
        __syncthreads();

        if (part == 0) {
            float fb[KNB]; int fi[KNB];
#pragma unroll
            for (int k = 0; k < KNB; k++) { fb[k] = 1e30f; fi[k] = 0; }
            for (int p = 0; p < 4; p++) {
                for (int k = 0; k < KNB; k++) {
                    float v = md[(qi*4 + p)*8 + k];
                    if (v >= fb[KNB-1]) break;
                    int vi = mi[(qi*4 + p)*8 + k];
#pragma unroll
                    for (int t = 0; t < KNB; t++) {
                        if (v < fb[t]) {
                            float tf = fb[t]; fb[t] = v; v = tf;
                            int   ti = fi[t]; fi[t] = vi; vi = ti;
                        }
                    }
                }
            }
            int cnt = 0;
#pragma unroll
            for (int k = 0; k < KNB; k++) cnt += (fb[k] <= RR2) ? 1 : 0;
#pragma unroll
            for (int k = 0; k < KNB; k++)
                gidx[((size_t)b*NN + q)*KNB + k] = fi[k];
            gcnt[b*NN + q] = cnt;
        }
    } else {
        // ---------------- weight prep ----------------
        const int t = blockIdx.x - 128;
        float* sA = sh;                                  // [64*132]

        if (t < 32) {
            const int p = t >> 3;
            const int layer = p >> 1;
            const float* A  = ((p & 1) ? Ws : Wd) + (size_t)layer*CC*CC;
            const float* Wm = Wa + (size_t)layer*CC*CC;
            const int r0 = ((t>>2)&1) * 64;
            const int n0 = (t&3) * 32;

            for (int i = tid; i < 64*32; i += 512) {
                int row = i >> 5, c4 = (i & 31) * 4;
                float4 v = *(const float4*)&A[(size_t)(r0+row)*CC + c4];
                sA[row*132 + c4+0] = v.x;
                sA[row*132 + c4+1] = v.y;
                sA[row*132 + c4+2] = v.z;
                sA[row*132 + c4+3] = v.w;
            }
            __syncthreads();

            if (tid < 256) {
                const int c  = n0 + (tid & 31);
                const int rr = (tid >> 5) * 8;
                float acc[8] = {0.f,0.f,0.f,0.f,0.f,0.f,0.f,0.f};
                for (int kk = 0; kk < 128; kk++) {
                    float w = Wm[(size_t)kk*CC + c];
#pragma unroll
                    for (int i = 0; i < 8; i++)
                        acc[i] = fmaf(sA[(rr+i)*132 + kk], w, acc[i]);
                }
#pragma unroll
                for (int i = 0; i < 8; i++) {
                    int row = r0 + rr + i;
                    int kc = row >> 5;
                    if (p & 1) {
                        int nc = 2*layer;
                        Wsv[(size_t)(nc*4 + kc)*4096 + poff_h(row & 31, c)] =
                            __float2half_rn(acc[i]);
                    } else {
                        Wda[(size_t)(layer*4 + kc)*4096 + poff_h(row & 31, c)] =
                            __float2half_rn(acc[i]);
                    }
                }
            }
        } else if (t < 64) {
            if (tid < 256) {
                const int tt = t - 32;
                const int l = tt >> 4, bx = tt & 15;
                for (int i = bx*256 + tid; i < CC*CC; i += 16*256) {
                    int row = i >> 7, c = i & 127;
                    int nc = 2*l + 1, kc = row >> 5;
                    Wsv[(size_t)(nc*4 + kc)*4096 + poff_h(row & 31, c)] =
                        __float2half_rn(Wlin[(size_t)l*CC*CC + i]);
                }
                if (bx == 0) {
                    for (int i = tid; i < 128; i += 256) {
                        bsv[256*l + i]       = 0.f;
                        bsv[256*l + 128 + i] = blin[l*CC + i];
                    }
                }
            }
        } else {
            if (tid < 256) {
                const int bx = t - 64;
                const int n = 2*CC*FFD;
                for (int i = bx*256 + tid; i < n; i += 64*256) {
                    {
                        int l = i >> 16, r2 = i & 65535;
                        int row = r2 >> 9, col = r2 & 511;
                        int nc = col >> 7, kc = row >> 5;
                        of1[(size_t)l*65536 + (size_t)(nc*4 + kc)*4096
                            + poff_h(row & 31, col & 127)] = __float2half_rn(Wf1[i]);
                    }
                    {
                        int l = i >> 16, r2 = i & 65535;
                        int row = r2 >> 7, col = r2 & 127;
                        int kc = row >> 5;
                        of2[(size_t)l*65536 + (size_t)kc*4096
                            + poff_h(row & 31, col)] = __float2half_rn(Wf2[i]);
                    }
                }
            }
        }
    }
}

// ---------------- merged SV (both layers) + P(layer0) GEMM ------------------
// grid (256, 5): y<4 -> SV tile y of kv_feat@WSV (Ncols 512);
//                y==4, x<128 -> P = q_feat@Wda0 + b_attn (Ncols 128).
// fp32 A converted at fragment load; fp16 out. MT=128, KD=128.
__global__ __launch_bounds__(256, 2) void gemm_svp(
    const float* __restrict__ Asv, const __half* __restrict__ Wsv,
    const float* __restrict__ bsv, __half* __restrict__ Csv,
    const float* __restrict__ Ap,  const __half* __restrict__ Wp,
    const float* __restrict__ bp,  __half* __restrict__ Cp)
{
    constexpr int AF = 128 * 40;
    constexpr int WF = 2048;
    extern __shared__ float dynsm[];
    float* Abuf[2]  = { dynsm,      dynsm + AF + WF };
    float* Wbuf[2]  = { dynsm + AF, dynsm + 2*AF + WF };

    const float* A; const __half* W; const float* bias; __half* C;
    int Ncols, n0;
    if (blockIdx.y < 4) {
        A = Asv; W = Wsv; bias = bsv; C = Csv; Ncols = 512; n0 = blockIdx.y*128;
    } else {
        if (blockIdx.x >= 128) return;
        A = Ap; W = Wp; bias = bp; C = Cp; Ncols = 128; n0 = 0;
    }

    const int m0 = blockIdx.x * 128;
    const int tid = threadIdx.x;
    const int lane = tid & 31, warp = tid >> 5;
    const int wm = (warp & 3) * 32, wn = (warp >> 2) * 64;
    const int nhalf = warp >> 2;
    const int gID = lane >> 2, tig = lane & 3;

    const __half* Wbase = W + (size_t)(n0 >> 7) * 4 * 4096;

    float acc[2][8][4];
#pragma unroll
    for (int mt = 0; mt < 2; mt++)
#pragma unroll
        for (int nt = 0; nt < 8; nt++)
#pragma unroll
            for (int c = 0; c < 4; c++) acc[mt][nt][c] = 0.f;

    auto issue = [&](int st, int ic) {
        const int kc = ic * 32;
#pragma unroll
        for (int r = 0; r < 4; r++) {
            int id = tid + r*256;
            int row = id >> 3, c4 = (id & 7) * 4;
            cp16(&Abuf[st][row*40 + c4], &A[(size_t)(m0+row)*128 + kc + c4]);
        }
        const __half* wsrc = Wbase + (size_t)ic * 4096;
#pragma unroll
        for (int r = 0; r < 2; r++) {
            int id = tid + r*256;
            cp16(&Wbuf[st][id*4], (const float*)(wsrc + id*8));
        }
    };

    issue(0, 0);
    CP_COMMIT;

    for (int it = 0; it < 4; ++it) {
        if (it + 1 < 4) { issue((it+1) & 1, it+1); CP_COMMIT; CP_WAIT1; }
        else CP_WAIT0;
        __syncthreads();
        const float*  Ac = Abuf[it & 1];
        const float4* Wf4 = (const float4*)Wbuf[it & 1];
#pragma unroll
        for (int s = 0; s < 2; s++) {
            uint32_t a[2][4];
#pragma unroll
            for (int mt = 0; mt < 2; mt++) {
                int r0 = wm + mt*16 + gID;
                const float* b0p = &Ac[r0*40 + s*16 + 2*tig];
                const float* b1p = &Ac[(r0+8)*40 + s*16 + 2*tig];
                float2 p0 = *(const float2*)b0p;
                float2 p1 = *(const float2*)b1p;
                float2 p2 = *(const float2*)(b0p + 8);
                float2 p3 = *(const float2*)(b1p + 8);
                a[mt][0] = cvt2h(p0.x, p0.y);
                a[mt][1] = cvt2h(p1.x, p1.y);
                a[mt][2] = cvt2h(p2.x, p2.y);
                a[mt][3] = cvt2h(p3.x, p3.y);
            }
#pragma unroll
            for (int u = 0; u < 4; u++) {
                float4 bq = Wf4[((s*2 + nhalf)*4 + u)*32 + lane];
                uint32_t be0 = __float_as_uint(bq.x), be1 = __float_as_uint(bq.y);
                uint32_t bo0 = __float_as_uint(bq.z), bo1 = __float_as_uint(bq.w);
#pragma unroll
                for (int mt = 0; mt < 2; mt++) {
                    mma_h(acc[mt][2*u],   a[mt], be0, be1);
                    mma_h(acc[mt][2*u+1], a[mt], bo0, bo1);
                }
            }
        }
        if (it + 1 < 4) __syncthreads();
    }

#pragma unroll
    for (int mt = 0; mt < 2; mt++) {
        int row = m0 + wm + mt*16 + gID;
#pragma unroll
        for (int nt = 0; nt < 8; nt++) {
            int col = n0 + wn + nt*8 + 2*tig;
            float b0v = bias[col], b1v = bias[col+1];
            *(__half2*)&C[(size_t)row*Ncols + col] =
                __floats2half2_rn(acc[mt][nt][0]+b0v, acc[mt][nt][1]+b1v);
            *(__half2*)&C[(size_t)(row+8)*Ncols + col] =
                __floats2half2_rn(acc[mt][nt][2]+b0v, acc[mt][nt][3]+b1v);
        }
    }
}

// ---------------- fp16 tensor-core GEMM, permuted-B, cp.async ---------------
// AH=0: A fp32 (smem stride 40 floats). AH=1: A fp16 (smem stride 56 halves).
// EPI: 0 = (+bias, fp16 out), 1 = (+bias, exact GELU, fp16 out),
//      2 = (+bias, +resid fp32, LayerNorm, fp32 out)
template<int KD, int MT, int EPI, int AH>
__global__ __launch_bounds__(256, 2) void gemm_h(
    const void* __restrict__ Ain, const __half* __restrict__ W,
    const float* __restrict__ bias, void* __restrict__ Cout, int Ncols,
    const float* __restrict__ resid,
    const float* __restrict__ lng, const float* __restrict__ lnb)
{
    constexpr int MTC = MT / 64;
    constexpr int AF = AH ? (MT * 28) : (MT * 40);
    constexpr int WF = 2048;
    extern __shared__ float dynsm[];
    float* Abuf[2]  = { dynsm,      dynsm + AF + WF };
    float* Wbuf[2]  = { dynsm + AF, dynsm + 2*AF + WF };
    __shared__ float rs1[128], rs2[128];

    const int m0 = blockIdx.x * MT;
    const int n0 = blockIdx.y * 128;
    const int tid = threadIdx.x;
    const int lane = tid & 31, warp = tid >> 5;
    const int wm = (warp & 3) * (MT/4), wn = (warp >> 2) * 64;
    const int nhalf = warp >> 2;
    const int gID = lane >> 2, tig = lane & 3;

    if (EPI == 2 && tid < MT) { rs1[tid] = 0.f; rs2[tid] = 0.f; }

    const __half* Wbase = W + (size_t)(n0 >> 7) * (KD/32) * 4096;
    const float*  Af = (const float*)Ain;
    const __half* Ah = (const __half*)Ain;

    float acc[MTC][8][4];
#pragma unroll
    for (int mt = 0; mt < MTC; mt++)
#pragma unroll
        for (int nt = 0; nt < 8; nt++)
#pragma unroll
            for (int c = 0; c < 4; c++) acc[mt][nt][c] = 0.f;

    auto issue = [&](int st, int ic) {
        const int kc = ic * 32;
        if (AH == 0) {
#pragma unroll
            for (int r = 0; r < MT/32; r++) {
                int id = tid + r*256;
                int row = id >> 3, c4 = (id & 7) * 4;
                cp16(&Abuf[st][row*40 + c4], &Af[(size_t)(m0+row)*KD + kc + c4]);
            }
        } else {
            __half* Ab = (__half*)Abuf[st];
#pragma unroll
            for (int r = 0; r < MT/64; r++) {
                int id = tid + r*256;
                int row = id >> 2, u = (id & 3) * 8;
                cp16(&Ab[row*56 + u], &Ah[(size_t)(m0+row)*KD + kc + u]);
            }
        }
        const __half* wsrc = Wbase + (size_t)ic * 4096;
#pragma unroll
        for (int r = 0; r < 2; r++) {
            int id = tid + r*256;
            cp16(&Wbuf[st][id*4], (const float*)(wsrc + id*8));
        }
    };

    constexpr int NIT = KD / 32;
    issue(0, 0);
    CP_COMMIT;

    for (int it = 0; it < NIT; ++it) {
        if (it + 1 < NIT) { issue((it+1) & 1, it+1); CP_COMMIT; CP_WAIT1; }
        else CP_WAIT0;
        __syncthreads();
        const float*  Ac = Abuf[it & 1];
        const __half* Ach = (const __half*)Abuf[it & 1];
        const float4* Wf4 = (const float4*)Wbuf[it & 1];
#pragma unroll
        for (int s = 0; s < 2; s++) {
            uint32_t a[MTC][4];
#pragma unroll
            for (int mt = 0; mt < MTC; mt++) {
                int r0 = wm + mt*16 + gID;
                if (AH == 0) {
                    const float* b0p = &Ac[r0*40 + s*16 + 2*tig];
                    const float* b1p = &Ac[(r0+8)*40 + s*16 + 2*tig];
                    float2 p0 = *(const float2*)b0p;
                    float2 p1 = *(const float2*)b1p;
                    float2 p2 = *(const float2*)(b0p + 8);
                    float2 p3 = *(const float2*)(b1p + 8);
                    a[mt][0] = cvt2h(p0.x, p0.y);
                    a[mt][1] = cvt2h(p1.x, p1.y);
                    a[mt][2] = cvt2h(p2.x, p2.y);
                    a[mt][3] = cvt2h(p3.x, p3.y);
                } else {
                    a[mt][0] = *(const uint32_t*)&Ach[r0*56 + s*16 + 2*tig];
                    a[mt][1] = *(const uint32_t*)&Ach[(r0+8)*56 + s*16 + 2*tig];
                    a[mt][2] = *(const uint32_t*)&Ach[r0*56 + s*16 + 2*tig + 8];
                    a[mt][3] = *(const uint32_t*)&Ach[(r0+8)*56 + s*16 + 2*tig + 8];
                }
            }
#pragma unroll
            for (int u = 0; u < 4; u++) {
                float4 bq = Wf4[((s*2 + nhalf)*4 + u)*32 + lane];
                uint32_t be0 = __float_as_uint(bq.x), be1 = __float_as_uint(bq.y);
                uint32_t bo0 = __float_as_uint(bq.z), bo1 = __float_as_uint(bq.w);
#pragma unroll
                for (int mt = 0; mt < MTC; mt++) {
                    mma_h(acc[mt][2*u],   a[mt], be0, be1);
                    mma_h(acc[mt][2*u+1], a[mt], bo0, bo1);
                }
            }
        }
        if (it + 1 < NIT) __syncthreads();
    }

    if (EPI != 2) {
        __half* Ch = (__half*)Cout;
#pragma unroll
        for (int mt = 0; mt < MTC; mt++) {
            int row = m0 + wm + mt*16 + gID;
#pragma unroll
            for (int nt = 0; nt < 8; nt++) {
                int col = n0 + wn + nt*8 + 2*tig;
                float b0v = bias ? bias[col]   : 0.f;
                float b1v = bias ? bias[col+1] : 0.f;
                float v0 = acc[mt][nt][0] + b0v;
                float v1 = acc[mt][nt][1] + b1v;
                float v2 = acc[mt][nt][2] + b0v;
                float v3 = acc[mt][nt][3] + b1v;
                if (EPI == 1) {
                    v0 = 0.5f*v0*(1.f + erff(v0*0.70710678118654752f));
                    v1 = 0.5f*v1*(1.f + erff(v1*0.70710678118654752f));
                    v2 = 0.5f*v2*(1.f + erff(v2*0.70710678118654752f));
                    v3 = 0.5f*v3*(1.f + erff(v3*0.70710678118654752f));
                }
                *(__half2*)&Ch[(size_t)row*Ncols + col] =
                    __floats2half2_rn(v0, v1);
                *(__half2*)&Ch[(size_t)(row+8)*Ncols + col] =
                    __floats2half2_rn(v2, v3);
            }
        }
    } else {
        float* Cf = (float*)Cout;
        float s1[MTC][2], s2[MTC][2];
#pragma unroll
        for (int mt = 0; mt < MTC; mt++) {
            s1[mt][0]=s1[mt][1]=s2[mt][0]=s2[mt][1]=0.f;
            int row = m0 + wm + mt*16 + gID;
#pragma unroll
            for (int nt = 0; nt < 8; nt++) {
                int col = wn + nt*8 + 2*tig;
                float b0v = bias[col], b1v = bias[col+1];
                float x0 = acc[mt][nt][0] + b0v + resid[(size_t)row*128 + col];
                float x1 = acc[mt][nt][1] + b1v + resid[(size_t)row*128 + col+1];
                float x2 = acc[mt][nt][2] + b0v + resid[(size_t)(row+8)*128 + col];
                float x3 = acc[mt][nt][3] + b1v + resid[(size_t)(row+8)*128 + col+1];
                acc[mt][nt][0]=x0; acc[mt][nt][1]=x1; acc[mt][nt][2]=x2; acc[mt][nt][3]=x3;
                s1[mt][0] += x0 + x1;       s1[mt][1] += x2 + x3;
                s2[mt][0] += x0*x0 + x1*x1; s2[mt][1] += x2*x2 + x3*x3;
            }
        }
#pragma unroll
        for (int mt = 0; mt < MTC; mt++)
#pragma unroll
            for (int h = 0; h < 2; h++) {
                s1[mt][h] += __shfl_xor_sync(0xffffffffu, s1[mt][h], 1);
                s1[mt][h] += __shfl_xor_sync(0xffffffffu, s1[mt][h], 2);
                s2[mt][h] += __shfl_xor_sync(0xffffffffu, s2[mt][h], 1);
                s2[mt][h] += __shfl_xor_sync(0xffffffffu, s2[mt][h], 2);
            }
        if (tig == 0) {
#pragma unroll
            for (int mt = 0; mt < MTC; mt++)
#pragma unroll
                for (int h = 0; h < 2; h++) {
                    int lr = wm + mt*16 + gID + h*8;
                    atomicAdd(&rs1[lr], s1[mt][h]);
                    atomicAdd(&rs2[lr], s2[mt][h]);
                }
        }
        __syncthreads();
#pragma unroll
        for (int mt = 0; mt < MTC; mt++) {
            int lr = wm + mt*16 + gID;
            float mu0 = rs1[lr]   * (1.f/128.f);
            float mu1 = rs1[lr+8] * (1.f/128.f);
            float rstd0 = rsqrtf(rs2[lr]  *(1.f/128.f) - mu0*mu0 + 1e-5f);
            float rstd1 = rsqrtf(rs2[lr+8]*(1.f/128.f) - mu1*mu1 + 1e-5f);
            int row = m0 + lr;
#pragma unroll
            for (int nt = 0; nt < 8; nt++) {
                int col = wn + nt*8 + 2*tig;
                float g0 = lng[col], g1 = lng[col+1];
                float bb0 = lnb[col], bb1 = lnb[col+1];
                float y0 = (acc[mt][nt][0]-mu0)*rstd0*g0 + bb0;
                float y1 = (acc[mt][nt][1]-mu0)*rstd0*g1 + bb1;
                float y2 = (acc[mt][nt][2]-mu1)*rstd1*g0 + bb0;
                float y3 = (acc[mt][nt][3]-mu1)*rstd1*g1 + bb1;
                *(float2*)&Cf[(size_t)row*128 + col]     = make_float2(y0, y1);
                *(float2*)&Cf[(size_t)(row+8)*128 + col] = make_float2(y2, y3);
            }
        }
    }
}

// ---------------- light attention: gather + softmax + residual + LN ---------
__global__ __launch_bounds__(256) void attn2_kernel(
    const __half* __restrict__ P, const __half* __restrict__ S,
    const __half* __restrict__ V, const int* __restrict__ gidx,
    const int* __restrict__ gcnt,
    const float* __restrict__ resid, float* __restrict__ out,
    const float* __restrict__ g1, const float* __restrict__ b1)
{
    const int warp = threadIdx.x >> 5, lane = threadIdx.x & 31;
    const int q = blockIdx.x * 8 + warp;
    const int b = q / NN;
    const int c0 = lane * 4;

    const __half2* pp = (const __half2*)&P[(size_t)q*CC + c0];
    float2 pa = __half22float2(pp[0]);
    float2 pb = __half22float2(pp[1]);
    const int kcnt = gcnt[q];
    int nid[KNB];
#pragma unroll
    for (int k = 0; k < KNB; k++) nid[k] = gidx[(size_t)q*KNB + k];

    float4 lg[KNB];
    float mx0 = -1e30f, mx1 = -1e30f, mx2 = -1e30f, mx3 = -1e30f;
#pragma unroll
    for (int k = 0; k < KNB; k++) {
        if (k < kcnt) {
            const __half2* sp2 = (const __half2*)&S[((size_t)b*LL + nid[k])*512 + c0];
            float2 sa = __half22float2(sp2[0]);
            float2 sb = __half22float2(sp2[1]);
            float4 l;
            l.x = fmaxf(pa.x - sa.x, 0.f);
            l.y = fmaxf(pa.y - sa.y, 0.f);
            l.z = fmaxf(pb.x - sb.x, 0.f);
            l.w = fmaxf(pb.y - sb.y, 0.f);
            lg[k] = l;
            mx0 = fmaxf(mx0, l.x); mx1 = fmaxf(mx1, l.y);
            mx2 = fmaxf(mx2, l.z); mx3 = fmaxf(mx3, l.w);
        }
    }

    float su0=0.f, su1=0.f, su2=0.f, su3=0.f;
    float up0=0.f, up1=0.f, up2=0.f, up3=0.f;
#pragma unroll
    for (int k = 0; k < KNB; k++) {
        if (k < kcnt) {
            const __half2* vp2 = (const __half2*)&V[((size_t)b*LL + nid[k])*512 + c0];
            float2 va = __half22float2(vp2[0]);
            float2 vb = __half22float2(vp2[1]);
            float w0 = expf(lg[k].x - mx0);
            float w1 = expf(lg[k].y - mx1);
            float w2 = expf(lg[k].z - mx2);
            float w3 = expf(lg[k].w - mx3);
            su0 += w0; su1 += w1; su2 += w2; su3 += w3;
            up0 = fmaf(w0, va.x, up0);
            up1 = fmaf(w1, va.y, up1);
            up2 = fmaf(w2, vb.x, up2);
            up3 = fmaf(w3, vb.y, up3);
        }
    }
    up0 /= fmaxf(su0, 1e-9f);
    up1 /= fmaxf(su1, 1e-9f);
    up2 /= fmaxf(su2, 1e-9f);
    up3 /= fmaxf(su3, 1e-9f);

    const float4 r4 = *(const float4*)&resid[(size_t)q*CC + c0];
    float x0 = r4.x + up0, x1 = r4.y + up1, x2 = r4.z + up2, x3 = r4.w + up3;

    float s = x0 + x1 + x2 + x3;
#pragma unroll
    for (int o = 16; o; o >>= 1) s += __shfl_xor_sync(0xffffffffu, s, o);
    float mu = s * (1.f/128.f);
    float d0 = x0-mu, d1 = x1-mu, d2 = x2-mu, d3 = x3-mu;
    float vs = d0*d0 + d1*d1 + d2*d2 + d3*d3;
#pragma unroll
    for (int o = 16; o; o >>= 1) vs += __shfl_xor_sync(0xffffffffu, vs, o);
    float rstd = rsqrtf(vs * (1.f/128.f) + 1e-5f);

    const float4 gg = *(const float4*)&g1[c0];
    const float4 bb = *(const float4*)&b1[c0];
    float4 y;
    y.x = d0*rstd*gg.x + bb.x;
    y.y = d1*rstd*gg.y + bb.y;
    y.z = d2*rstd*gg.z + bb.z;
    y.w = d3*rstd*gg.w + bb.w;
    *(float4*)&out[(size_t)q*CC + c0] = y;
}

// ---------------- launch ----------------------------------------------------
extern "C" void kernel_launch(void* const* d_in, const int* in_sizes, int n_in,
                              void* d_out, int out_size)
{
    const float*         q_xyz  = (const float*)d_in[0];
    const float*         q_feat = (const float*)d_in[1];
    const float*         kv_xyz = (const float*)d_in[2];
    const float*         kv_feat= (const float*)d_in[3];
    const unsigned char* kv_pad = (const unsigned char*)d_in[4];
    const float* W_lin  = (const float*)d_in[5];
    const float* b_lin  = (const float*)d_in[6];
    const float* W_src  = (const float*)d_in[7];
    const float* W_dst  = (const float*)d_in[8];
    const float* W_attn = (const float*)d_in[9];
    const float* b_attn = (const float*)d_in[10];
    const float* ln1_g  = (const float*)d_in[11];
    const float* ln1_b  = (const float*)d_in[12];
    const float* W_ff1  = (const float*)d_in[13];
    const float* b_ff1  = (const float*)d_in[14];
    const float* W_ff2  = (const float*)d_in[15];
    const float* b_ff2  = (const float*)d_in[16];
    const float* ln2_g  = (const float*)d_in[17];
    const float* ln2_b  = (const float*)d_in[18];
    float* out = (float*)d_out;

    void *p_idx, *p_cnt, *p_sv, *p_P, *p_h, *p_wda, *p_wsv, *p_bsv, *p_wf1, *p_wf2;
    cudaGetSymbolAddress(&p_idx, g_idx);
    cudaGetSymbolAddress(&p_cnt, g_cnt);
    cudaGetSymbolAddress(&p_sv,  g_SV);
    cudaGetSymbolAddress(&p_P,   g_P);
    cudaGetSymbolAddress(&p_h,   g_h);
    cudaGetSymbolAddress(&p_wda, g_wda);
    cudaGetSymbolAddress(&p_wsv, g_wsv);
    cudaGetSymbolAddress(&p_bsv, g_bsv);
    cudaGetSymbolAddress(&p_wf1, g_wf1);
    cudaGetSymbolAddress(&p_wf2, g_wf2);
    int*    idx_p = (int*)p_idx;
    int*    cnt_p = (int*)p_cnt;
    __half* sv_p  = (__half*)p_sv;
    __half* P_p   = (__half*)p_P;
    __half* h_p   = (__half*)p_h;
    __half* wda_p = (__half*)p_wda;
    __half* wsv_p = (__half*)p_wsv;
    float*  bsv_p = (float*)p_bsv;
    __half* wf1_p = (__half*)p_wf1;
    __half* wf2_p = (__half*)p_wf2;

    const int PRE_SMEM = 3*LL*4 + LL + 512*8*4*2;            // 86016
    const int SM128A0 = (2*(128*40) + 2*2048)*4;             // 57344
    const int SM64A0  = (2*(64*40)  + 2*2048)*4;             // 36864
    const int SM64A1  = (2*(64*28)  + 2*2048)*4;             // 30720
    cudaFuncSetAttribute(pre_kernel, cudaFuncAttributeMaxDynamicSharedMemorySize, PRE_SMEM);
    cudaFuncSetAttribute(gemm_svp,            cudaFuncAttributeMaxDynamicSharedMemorySize, SM128A0);
    cudaFuncSetAttribute(gemm_h<128,128,1,0>, cudaFuncAttributeMaxDynamicSharedMemorySize, SM128A0);
    cudaFuncSetAttribute(gemm_h<128,64,0,0>,  cudaFuncAttributeMaxDynamicSharedMemorySize, SM64A0);
    cudaFuncSetAttribute(gemm_h<512,64,2,1>,  cudaFuncAttributeMaxDynamicSharedMemorySize, SM64A1);

    const int BN = BB*NN;   // 16384

    // fused kNN + weight prep (one launch)
    pre_kernel<<<256, 512, PRE_SMEM>>>(
        q_xyz, kv_xyz, kv_pad, idx_p, cnt_p,
        W_dst, W_src, W_attn, W_lin, b_lin, W_ff1, W_ff2,
        wda_p, wsv_p, bsv_p, wf1_p, wf2_p);

    // merged: SV (both layers) + P(layer 0)
    gemm_svp<<<dim3(256, 5), 256, SM128A0>>>(
        kv_feat, wsv_p, bsv_p, sv_p,
        q_feat, wda_p, b_attn, P_p);

    for (int l = 0; l < 2; l++) {
        const size_t oC  = (size_t)l * CC;
        const size_t oF  = (size_t)l * FFD;
        const float* in_l = (l == 0) ? q_feat : out;

        if (l == 1) {
            // P = out @ Wda1 + b_attn1  (fp16 out)
            gemm_h<128,64,0,0><<<dim3(BN/64, 1), 256, SM64A0>>>(
                out, wda_p + (size_t)4*4096, b_attn + oC, P_p, CC,
                nullptr, nullptr, nullptr);
        }
        // attention gather/softmax + residual + LN1
        attn2_kernel<<<BN/8, 256>>>(
            P_p, sv_p + 256*l, sv_p + 256*l + 128, idx_p, cnt_p,
            in_l, out, ln1_g + oC, ln1_b + oC);
        // h = gelu(out @ W_ff1 + b_ff1)  (fp16 out)
        gemm_h<128,128,1,0><<<dim3(BN/128, FFD/128), 256, SM128A0>>>(
            out, wf1_p + (size_t)l*65536, b_ff1 + oF, h_p, FFD,
            nullptr, nullptr, nullptr);
        // out = LN2(out + h @ W_ff2 + b_ff2)  (A = h fp16)
        gemm_h<512,64,2,1><<<dim3(BN/64, 1), 256, SM64A1>>>(
            h_p, wf2_p + (size_t)l*65536, b_ff2 + oC, out, CC,
            out, ln2_g + oC, ln2_b + oC);
    }
}